// round 11
// baseline (speedup 1.0000x reference)
#include <cuda_runtime.h>
#include <cuda_fp16.h>

#define D_FEAT 64
#define MAX_NODES 100000

// Scratch (static __device__ arrays -- no allocation).
__device__ int   g_row_ptr[MAX_NODES + 1];
__device__ uint2 g_x16[MAX_NODES * 16];   // fp16 rows: 128B = 16 x uint2 per row

// Fused prep: blocks [0, rp_blocks) build row_ptr from the sorted targets;
// remaining blocks convert x (f32) -> g_x16 (fp16), lane-strided coalesced.
__global__ __launch_bounds__(256) void prep_kernel(
    const float4* __restrict__ xf4, int n_f4,
    const int* __restrict__ tgt, int n_edges, int n_nodes, int rp_blocks)
{
    const int b = (int)blockIdx.x;
    if (b < rp_blocks) {
        const int e = b * 256 + threadIdx.x;
        if (e >= n_edges) return;
        const int cur  = __ldg(tgt + e);
        const int prev = (e == 0) ? -1 : __ldg(tgt + e - 1);
        for (int v = prev + 1; v <= cur; ++v) g_row_ptr[v] = e;
        if (e == n_edges - 1) {
            for (int v = cur + 1; v <= n_nodes; ++v) g_row_ptr[v] = n_edges;
        }
    } else {
        // 4 float4 per thread, lane-strided (+32) -> fully coalesced LDG.128.
        const int t0 = (b - rp_blocks) * 256 + threadIdx.x;
        const int base = (t0 >> 5) * 128 + (t0 & 31);
        #pragma unroll 4
        for (int k = 0; k < 4; ++k) {
            const int i = base + k * 32;
            if (i < n_f4) {
                const float4 a = __ldg(xf4 + i);
                __half2 h0 = __floats2half2_rn(a.x, a.y);
                __half2 h1 = __floats2half2_rn(a.z, a.w);
                uint2 o;
                o.x = *reinterpret_cast<unsigned int*>(&h0);
                o.y = *reinterpret_cast<unsigned int*>(&h1);
                g_x16[i] = o;
            }
        }
    }
}

__device__ __forceinline__ __half2 h2of(unsigned int u) {
    return *reinterpret_cast<__half2*>(&u);
}
__device__ __forceinline__ unsigned int uof(__half2 h) {
    return *reinterpret_cast<unsigned int*>(&h);
}

// One warp per output node (R7 structure). Half-warp h serves edges of parity
// h; lane owns 4 features as one uint2 (4 fp16). Arithmetic: weights are
// pre-converted to half2 ONCE per 32-edge batch and broadcast as bits; each
// edge is 2 HFMA2 into a single fp16 accumulator pair, folded to f32 every
// 8 edges (chain depth 4). Per-edge issue slots drop ~12 -> ~7.
__global__ __launch_bounds__(128, 14) void mp_gather_kernel(
    const float* __restrict__ ev,   // [n_edges]
    const int*   __restrict__ src,  // [n_edges]
    float*       __restrict__ out,  // [n_nodes, 64]
    int n_nodes)
{
    const int warp = (blockIdx.x * blockDim.x + threadIdx.x) >> 5;
    if (warp >= n_nodes) return;
    const int lane = threadIdx.x & 31;
    const int half = lane >> 4;
    const int hl   = lane & 15;
    const int node = warp;

    const int start = __ldg(&g_row_ptr[node]);
    const int end   = __ldg(&g_row_ptr[node + 1]);

    const uint2* __restrict__ xh = g_x16;   // row = 16 uint2
    float a0 = 0.f, a1 = 0.f, a2 = 0.f, a3 = 0.f;
    const __half2 hzero = __floats2half2_rn(0.f, 0.f);

    for (int base = start; base < end; base += 32) {
        const int cnt = min(32, end - base);
        // Cooperative metadata load; weight converted to half2 once per batch.
        int          s_l  = 0;
        unsigned int wh_l = 0u;
        if (lane < cnt) {
            s_l = __ldg(src + base + lane);
            const float w = __ldg(ev + base + lane);
            wh_l = uof(__float2half2_rn(w));
        }

        const int full = cnt >> 1;   // complete pairs (both parities valid)
        int k = 0;

        // Main path: 4 pairs/step; fp16 accumulate (chain depth 4), fold to f32.
        for (; k + 4 <= full; k += 4) {
            const int j0 = 2 * (k + 0) + half;
            const int j1 = 2 * (k + 1) + half;
            const int j2 = 2 * (k + 2) + half;
            const int j3 = 2 * (k + 3) + half;
            const int s0 = __shfl_sync(0xffffffffu, s_l, j0);
            const int s1 = __shfl_sync(0xffffffffu, s_l, j1);
            const int s2 = __shfl_sync(0xffffffffu, s_l, j2);
            const int s3 = __shfl_sync(0xffffffffu, s_l, j3);
            const uint2 r0 = __ldg(&xh[(size_t)s0 * 16 + hl]);
            const uint2 r1 = __ldg(&xh[(size_t)s1 * 16 + hl]);
            const uint2 r2 = __ldg(&xh[(size_t)s2 * 16 + hl]);
            const uint2 r3 = __ldg(&xh[(size_t)s3 * 16 + hl]);
            const __half2 w0 = h2of(__shfl_sync(0xffffffffu, wh_l, j0));
            const __half2 w1 = h2of(__shfl_sync(0xffffffffu, wh_l, j1));
            const __half2 w2 = h2of(__shfl_sync(0xffffffffu, wh_l, j2));
            const __half2 w3 = h2of(__shfl_sync(0xffffffffu, wh_l, j3));
            __half2 T0 = hzero, T1 = hzero;
            T0 = __hfma2(w0, h2of(r0.x), T0); T1 = __hfma2(w0, h2of(r0.y), T1);
            T0 = __hfma2(w1, h2of(r1.x), T0); T1 = __hfma2(w1, h2of(r1.y), T1);
            T0 = __hfma2(w2, h2of(r2.x), T0); T1 = __hfma2(w2, h2of(r2.y), T1);
            T0 = __hfma2(w3, h2of(r3.x), T0); T1 = __hfma2(w3, h2of(r3.y), T1);
            const float2 f0 = __half22float2(T0);
            const float2 f1 = __half22float2(T1);
            a0 += f0.x; a1 += f0.y; a2 += f1.x; a3 += f1.y;
        }

        // Tail: remaining pairs (<=3) + odd edge, one fp16 chain (depth <=4).
        __half2 T0 = hzero, T1 = hzero;
        for (; k < full; ++k) {
            const int j = 2 * k + half;
            const int     s = __shfl_sync(0xffffffffu, s_l, j);
            const __half2 w = h2of(__shfl_sync(0xffffffffu, wh_l, j));
            const uint2 r = __ldg(&xh[(size_t)s * 16 + hl]);
            T0 = __hfma2(w, h2of(r.x), T0);
            T1 = __hfma2(w, h2of(r.y), T1);
        }
        if (cnt & 1) {
            const int j = cnt - 1;
            const int    s  = __shfl_sync(0xffffffffu, s_l, j);
            unsigned int wb = __shfl_sync(0xffffffffu, wh_l, j);
            if (half) wb = 0u;   // half 1 contributes zero
            const uint2 r = __ldg(&xh[(size_t)s * 16 + hl]);
            T0 = __hfma2(h2of(wb), h2of(r.x), T0);
            T1 = __hfma2(h2of(wb), h2of(r.y), T1);
        }
        const float2 f0 = __half22float2(T0);
        const float2 f1 = __half22float2(T1);
        a0 += f0.x; a1 += f0.y; a2 += f1.x; a3 += f1.y;
    }

    // Combine the two half-warp partial sums (f32).
    a0 += __shfl_xor_sync(0xffffffffu, a0, 16);
    a1 += __shfl_xor_sync(0xffffffffu, a1, 16);
    a2 += __shfl_xor_sync(0xffffffffu, a2, 16);
    a3 += __shfl_xor_sync(0xffffffffu, a3, 16);

    if (half == 0) {
        float4* __restrict__ of4 = (float4*)out;
        of4[(size_t)node * 16 + hl] = make_float4(a0, a1, a2, a3);
    }
}

extern "C" void kernel_launch(void* const* d_in, const int* in_sizes, int n_in,
                              void* d_out, int out_size) {
    const float* x   = (const float*)d_in[0];
    const float* ev  = (const float*)d_in[1];
    const int*   tgt = (const int*)d_in[2];
    const int*   src = (const int*)d_in[3];
    float* out = (float*)d_out;

    const int n_edges = in_sizes[1];
    const int n_nodes = out_size / D_FEAT;
    const int n_f4    = n_nodes * (D_FEAT / 4);

    const int rp_blocks = (n_edges + 255) / 256;
    const int cv_blocks = (n_f4 + 1023) / 1024;      // 4 float4/thread
    prep_kernel<<<rp_blocks + cv_blocks, 256>>>(
        (const float4*)x, n_f4, tgt, n_edges, n_nodes, rp_blocks);

    const int threads = 128;
    const int blocks  = (n_nodes * 32 + threads - 1) / threads;
    mp_gather_kernel<<<blocks, threads>>>(ev, src, out, n_nodes);
}

// round 12
// speedup vs baseline: 1.3055x; 1.3055x over previous
#include <cuda_runtime.h>
#include <cuda_fp16.h>

#define D_FEAT 64
#define MAX_NODES 100000

// Scratch (static __device__ arrays -- no allocation).
__device__ int   g_row_ptr[MAX_NODES + 1];
__device__ uint2 g_x16[MAX_NODES * 16];   // fp16 rows: 128B = 16 x uint2 per row

// Fused prep: blocks [0, rp_blocks) build row_ptr from the sorted targets;
// remaining blocks convert x (f32) -> g_x16 (fp16), lane-strided coalesced.
__global__ __launch_bounds__(256) void prep_kernel(
    const float4* __restrict__ xf4, int n_f4,
    const int* __restrict__ tgt, int n_edges, int n_nodes, int rp_blocks)
{
    const int b = (int)blockIdx.x;
    if (b < rp_blocks) {
        const int e = b * 256 + threadIdx.x;
        if (e >= n_edges) return;
        const int cur  = __ldg(tgt + e);
        const int prev = (e == 0) ? -1 : __ldg(tgt + e - 1);
        for (int v = prev + 1; v <= cur; ++v) g_row_ptr[v] = e;
        if (e == n_edges - 1) {
            for (int v = cur + 1; v <= n_nodes; ++v) g_row_ptr[v] = n_edges;
        }
    } else {
        // 4 float4 per thread, lane-strided (+32) -> fully coalesced LDG.128.
        const int t0 = (b - rp_blocks) * 256 + threadIdx.x;
        const int base = (t0 >> 5) * 128 + (t0 & 31);
        #pragma unroll 4
        for (int k = 0; k < 4; ++k) {
            const int i = base + k * 32;
            if (i < n_f4) {
                const float4 a = __ldg(xf4 + i);
                __half2 h0 = __floats2half2_rn(a.x, a.y);
                __half2 h1 = __floats2half2_rn(a.z, a.w);
                uint2 o;
                o.x = *reinterpret_cast<unsigned int*>(&h0);
                o.y = *reinterpret_cast<unsigned int*>(&h1);
                g_x16[i] = o;
            }
        }
    }
}

__device__ __forceinline__ __half2 h2of(unsigned int u) {
    return *reinterpret_cast<__half2*>(&u);
}
__device__ __forceinline__ unsigned int uof(__half2 h) {
    return *reinterpret_cast<unsigned int*>(&h);
}

// One warp per output node (R7 structure). Half-warp h serves edges of parity
// h; lane owns 4 features as one uint2 (4 fp16). Weights are pre-converted to
// half2 ONCE per 32-edge batch and shuffled as bits; each edge is 2 HFMA2
// into a single fp16 accumulator pair, folded to f32 every 8 edges (chain
// depth 4). NOTE: no min-blocks clause -- R11 proved forcing occupancy here
// makes ptxas spill the in-flight temporaries (L1 48%->81%, +16us).
__global__ __launch_bounds__(128) void mp_gather_kernel(
    const float* __restrict__ ev,   // [n_edges]
    const int*   __restrict__ src,  // [n_edges]
    float*       __restrict__ out,  // [n_nodes, 64]
    int n_nodes)
{
    const int warp = (blockIdx.x * blockDim.x + threadIdx.x) >> 5;
    if (warp >= n_nodes) return;
    const int lane = threadIdx.x & 31;
    const int half = lane >> 4;
    const int hl   = lane & 15;
    const int node = warp;

    const int start = __ldg(&g_row_ptr[node]);
    const int end   = __ldg(&g_row_ptr[node + 1]);

    const uint2* __restrict__ xh = g_x16;   // row = 16 uint2
    float a0 = 0.f, a1 = 0.f, a2 = 0.f, a3 = 0.f;
    const __half2 hzero = __floats2half2_rn(0.f, 0.f);

    for (int base = start; base < end; base += 32) {
        const int cnt = min(32, end - base);
        // Cooperative metadata load; weight converted to half2 once per batch.
        int          s_l  = 0;
        unsigned int wh_l = 0u;
        if (lane < cnt) {
            s_l = __ldg(src + base + lane);
            const float w = __ldg(ev + base + lane);
            wh_l = uof(__float2half2_rn(w));
        }

        const int full = cnt >> 1;   // complete pairs (both parities valid)
        int k = 0;

        // Main path: 4 pairs/step; fp16 accumulate (chain depth 4), fold to f32.
        for (; k + 4 <= full; k += 4) {
            const int j0 = 2 * (k + 0) + half;
            const int j1 = 2 * (k + 1) + half;
            const int j2 = 2 * (k + 2) + half;
            const int j3 = 2 * (k + 3) + half;
            const int s0 = __shfl_sync(0xffffffffu, s_l, j0);
            const int s1 = __shfl_sync(0xffffffffu, s_l, j1);
            const int s2 = __shfl_sync(0xffffffffu, s_l, j2);
            const int s3 = __shfl_sync(0xffffffffu, s_l, j3);
            const uint2 r0 = __ldg(&xh[(size_t)s0 * 16 + hl]);
            const uint2 r1 = __ldg(&xh[(size_t)s1 * 16 + hl]);
            const uint2 r2 = __ldg(&xh[(size_t)s2 * 16 + hl]);
            const uint2 r3 = __ldg(&xh[(size_t)s3 * 16 + hl]);
            const __half2 w0 = h2of(__shfl_sync(0xffffffffu, wh_l, j0));
            const __half2 w1 = h2of(__shfl_sync(0xffffffffu, wh_l, j1));
            const __half2 w2 = h2of(__shfl_sync(0xffffffffu, wh_l, j2));
            const __half2 w3 = h2of(__shfl_sync(0xffffffffu, wh_l, j3));
            __half2 T0 = hzero, T1 = hzero;
            T0 = __hfma2(w0, h2of(r0.x), T0); T1 = __hfma2(w0, h2of(r0.y), T1);
            T0 = __hfma2(w1, h2of(r1.x), T0); T1 = __hfma2(w1, h2of(r1.y), T1);
            T0 = __hfma2(w2, h2of(r2.x), T0); T1 = __hfma2(w2, h2of(r2.y), T1);
            T0 = __hfma2(w3, h2of(r3.x), T0); T1 = __hfma2(w3, h2of(r3.y), T1);
            const float2 f0 = __half22float2(T0);
            const float2 f1 = __half22float2(T1);
            a0 += f0.x; a1 += f0.y; a2 += f1.x; a3 += f1.y;
        }

        // Tail: remaining pairs (<=3) + odd edge, one fp16 chain (depth <=4).
        __half2 T0 = hzero, T1 = hzero;
        for (; k < full; ++k) {
            const int j = 2 * k + half;
            const int     s = __shfl_sync(0xffffffffu, s_l, j);
            const __half2 w = h2of(__shfl_sync(0xffffffffu, wh_l, j));
            const uint2 r = __ldg(&xh[(size_t)s * 16 + hl]);
            T0 = __hfma2(w, h2of(r.x), T0);
            T1 = __hfma2(w, h2of(r.y), T1);
        }
        if (cnt & 1) {
            const int j = cnt - 1;
            const int    s  = __shfl_sync(0xffffffffu, s_l, j);
            unsigned int wb = __shfl_sync(0xffffffffu, wh_l, j);
            if (half) wb = 0u;   // half 1 contributes zero
            const uint2 r = __ldg(&xh[(size_t)s * 16 + hl]);
            T0 = __hfma2(h2of(wb), h2of(r.x), T0);
            T1 = __hfma2(h2of(wb), h2of(r.y), T1);
        }
        const float2 f0 = __half22float2(T0);
        const float2 f1 = __half22float2(T1);
        a0 += f0.x; a1 += f0.y; a2 += f1.x; a3 += f1.y;
    }

    // Combine the two half-warp partial sums (f32).
    a0 += __shfl_xor_sync(0xffffffffu, a0, 16);
    a1 += __shfl_xor_sync(0xffffffffu, a1, 16);
    a2 += __shfl_xor_sync(0xffffffffu, a2, 16);
    a3 += __shfl_xor_sync(0xffffffffu, a3, 16);

    if (half == 0) {
        float4* __restrict__ of4 = (float4*)out;
        of4[(size_t)node * 16 + hl] = make_float4(a0, a1, a2, a3);
    }
}

extern "C" void kernel_launch(void* const* d_in, const int* in_sizes, int n_in,
                              void* d_out, int out_size) {
    const float* x   = (const float*)d_in[0];
    const float* ev  = (const float*)d_in[1];
    const int*   tgt = (const int*)d_in[2];
    const int*   src = (const int*)d_in[3];
    float* out = (float*)d_out;

    const int n_edges = in_sizes[1];
    const int n_nodes = out_size / D_FEAT;
    const int n_f4    = n_nodes * (D_FEAT / 4);

    const int rp_blocks = (n_edges + 255) / 256;
    const int cv_blocks = (n_f4 + 1023) / 1024;      // 4 float4/thread
    prep_kernel<<<rp_blocks + cv_blocks, 256>>>(
        (const float4*)x, n_f4, tgt, n_edges, n_nodes, rp_blocks);

    const int threads = 128;
    const int blocks  = (n_nodes * 32 + threads - 1) / threads;
    mp_gather_kernel<<<blocks, threads>>>(ev, src, out, n_nodes);
}